// round 1
// baseline (speedup 1.0000x reference)
#include <cuda_runtime.h>
#include <math.h>

#define B 2048
#define C1 64
#define A1_HW 225            // 15*15 pooled
#define A1_PER (C1*A1_HW)    // 14400
#define C2 32
#define A2_HW 36             // 6*6 pooled
#define A2_PER (C2*A2_HW)    // 1152
#define C3 32
#define H_PER 512            // 32*4*4
#define KCB 100
#define BN_EPS 1e-5f

// output layout: recon[B*512], h[B*512], vq_loss[1], logp[B*10]
#define RECON_OFF 0
#define H_OFF     (B*H_PER)
#define LOSS_OFF  (2*B*H_PER)
#define LP_OFF    (2*B*H_PER + 1)

// ---------------- device scratch (no allocations allowed) ----------------
__device__ float g_a1[B*A1_PER];     // conv1+pool+relu (pre-BN)
__device__ float g_a2[B*A2_PER];     // conv2+pool+relu (pre-BN)
__device__ float g_hp[B*H_PER];      // conv3+relu (pre-BN)
__device__ float g_sum1[C1], g_ssq1[C1], g_g1[C1], g_b1[C1];
__device__ float g_sum2[C2], g_ssq2[C2], g_g2[C2], g_b2[C2];
__device__ float g_sum3[C3], g_ssq3[C3], g_g3[C3], g_b3[C3];
__device__ float g_cbsq[KCB];
__device__ float g_vq;

__device__ __forceinline__ float wredsum(float v) {
#pragma unroll
    for (int o = 16; o; o >>= 1) v += __shfl_down_sync(0xffffffffu, v, o);
    return v;
}

// FMA update of a 2x2 pool window of 3x3 conv outputs from a 4x4 patch
__device__ __forceinline__ void win_fma(float acc[4], const float wv[9], const float p[4][4]) {
#pragma unroll
    for (int ky = 0; ky < 3; ky++)
#pragma unroll
        for (int kx = 0; kx < 3; kx++) {
            float w = wv[ky*3+kx];
            acc[0] = fmaf(w, p[ky  ][kx  ], acc[0]);
            acc[1] = fmaf(w, p[ky  ][kx+1], acc[1]);
            acc[2] = fmaf(w, p[ky+1][kx  ], acc[2]);
            acc[3] = fmaf(w, p[ky+1][kx+1], acc[3]);
        }
}

// ---------------- init: zero stats, codebook squared norms ----------------
__global__ void k_init(const float* __restrict__ cb) {
    int t = threadIdx.x;
    if (t < C1) { g_sum1[t] = 0.f; g_ssq1[t] = 0.f; }
    if (t < C2) { g_sum2[t] = 0.f; g_ssq2[t] = 0.f; g_sum3[t] = 0.f; g_ssq3[t] = 0.f; }
    if (t == 0) g_vq = 0.f;
    if (t < KCB) {
        float s = 0.f;
#pragma unroll
        for (int c = 0; c < 32; c++) { float v = cb[t*32+c]; s = fmaf(v, v, s); }
        g_cbsq[t] = s;
    }
}

// ---------------- conv1: 3->64, 3x3 VALID on 32x32, maxpool2, relu ----------------
__global__ void __launch_bounds__(256) k_conv1(const float* __restrict__ x,
                                               const float* __restrict__ w,
                                               const float* __restrict__ bias) {
    __shared__ float sx[3*1024];      // [ci][32*32]
    __shared__ float sw[3*64*12];     // repacked [ci][co][12]
    int n = blockIdx.x, tid = threadIdx.x;

    const float4* x4 = (const float4*)(x + (size_t)n * 3072);
    float4* sx4 = (float4*)sx;
    for (int i = tid; i < 768; i += 256) sx4[i] = x4[i];
    for (int i = tid; i < 1728; i += 256) {
        int co = i / 27, r = i % 27, ci = r / 9, k = r % 9;
        sw[(ci*64 + co)*12 + k] = w[i];
    }
    __syncthreads();

    for (int it = tid; it < 1800; it += 256) {      // 225 pos x 8 channel-groups
        int pos = it % 225, cg = it / 225;
        int py2 = (pos / 15) * 2, px2 = (pos % 15) * 2;
        float acc[8][4];
#pragma unroll
        for (int a = 0; a < 8; a++)
#pragma unroll
            for (int b = 0; b < 4; b++) acc[a][b] = 0.f;

#pragma unroll
        for (int ci = 0; ci < 3; ci++) {
            float p[4][4];
            const float* sp = sx + ci*1024 + py2*32 + px2;
#pragma unroll
            for (int r = 0; r < 4; r++)
#pragma unroll
                for (int c = 0; c < 4; c++) p[r][c] = sp[r*32 + c];
            const float* wb = sw + (ci*64 + cg*8)*12;
#pragma unroll
            for (int cl = 0; cl < 8; cl++) {
                const float4* w4 = (const float4*)(wb + cl*12);
                float4 wa = w4[0], wc = w4[1];
                float wv[9] = {wa.x, wa.y, wa.z, wa.w, wc.x, wc.y, wc.z, wc.w, wb[cl*12+8]};
                win_fma(acc[cl], wv, p);
            }
        }
#pragma unroll
        for (int cl = 0; cl < 8; cl++) {
            int co = cg*8 + cl;
            float v = fmaxf(fmaxf(acc[cl][0], acc[cl][1]), fmaxf(acc[cl][2], acc[cl][3])) + bias[co];
            g_a1[(size_t)n*A1_PER + co*225 + pos] = fmaxf(v, 0.f);
        }
    }
}

// ---------------- per-channel sum/sumsq over (N,HW) ----------------
__global__ void k_stats(int stage) {
    const float* a; float* sum; float* ssq; int C, HW;
    if (stage == 0)      { a = g_a1; sum = g_sum1; ssq = g_ssq1; C = 64; HW = 225; }
    else if (stage == 1) { a = g_a2; sum = g_sum2; ssq = g_ssq2; C = 32; HW = 36; }
    else                 { a = g_hp; sum = g_sum3; ssq = g_ssq3; C = 32; HW = 16; }
    int c = blockIdx.x, tid = threadIdx.x;
    float s = 0.f, s2 = 0.f;
    for (int n = blockIdx.y; n < B; n += gridDim.y) {
        const float* p = a + ((size_t)n*C + c)*HW;
        for (int i = tid; i < HW; i += blockDim.x) { float v = p[i]; s += v; s2 = fmaf(v, v, s2); }
    }
    __shared__ float rs[8], rq[8];
    s = wredsum(s); s2 = wredsum(s2);
    int wid = tid >> 5, lane = tid & 31;
    if (lane == 0) { rs[wid] = s; rq[wid] = s2; }
    __syncthreads();
    if (tid == 0) {
        float a1 = 0.f, a2 = 0.f;
        for (int w = 0; w < 8; w++) { a1 += rs[w]; a2 += rq[w]; }
        atomicAdd(sum + c, a1); atomicAdd(ssq + c, a2);
    }
}

// ---------------- BN affine coefficients: y = x*g + b ----------------
__global__ void k_bncoef(int stage, const float* __restrict__ scale,
                         const float* __restrict__ bias, float count) {
    float *sum, *ssq, *g, *bo; int C;
    if (stage == 0)      { sum = g_sum1; ssq = g_ssq1; g = g_g1; bo = g_b1; C = 64; }
    else if (stage == 1) { sum = g_sum2; ssq = g_ssq2; g = g_g2; bo = g_b2; C = 32; }
    else                 { sum = g_sum3; ssq = g_ssq3; g = g_g3; bo = g_b3; C = 32; }
    int c = threadIdx.x;
    if (c < C) {
        float m = sum[c] / count;
        float v = fmaxf(ssq[c] / count - m*m, 0.f);
        float gg = scale[c] / sqrtf(v + BN_EPS);
        g[c] = gg;
        bo[c] = bias[c] - m * gg;
    }
}

// ---------------- conv2: 64->32 on bn1(a1) 15x15, pool->6x6, relu ----------------
#define CONV2_SMEM ((14400 + 24576) * 4)
__global__ void __launch_bounds__(288) k_conv2(const float* __restrict__ w,
                                               const float* __restrict__ bias) {
    extern __shared__ float sm[];
    float* sin = sm;           // 14400: bn1-applied input [64][225]
    float* sw  = sm + 14400;   // 24576: repacked [ci][co][12]
    int n = blockIdx.x, tid = threadIdx.x;

    for (int i = tid; i < A1_PER; i += 288) {
        int c = i / 225;
        sin[i] = fmaf(g_a1[(size_t)n*A1_PER + i], g_g1[c], g_b1[c]);
    }
    for (int i = tid; i < 18432; i += 288) {
        int co = i / 576, r = i % 576, ci = r / 9, k = r % 9;
        sw[(ci*32 + co)*12 + k] = w[i];
    }
    __syncthreads();

    int pos = tid % 36, grp = tid / 36;                 // 8 groups x 4 co
    int py2 = (pos / 6) * 2, px2 = (pos % 6) * 2;
    float acc[4][4];
#pragma unroll
    for (int a = 0; a < 4; a++)
#pragma unroll
        for (int b = 0; b < 4; b++) acc[a][b] = 0.f;

    for (int ci = 0; ci < 64; ci++) {
        float p[4][4];
        const float* sp = sin + ci*225 + py2*15 + px2;
#pragma unroll
        for (int r = 0; r < 4; r++)
#pragma unroll
            for (int c = 0; c < 4; c++) p[r][c] = sp[r*15 + c];
        const float* wb = sw + (ci*32 + grp*4)*12;
#pragma unroll
        for (int cl = 0; cl < 4; cl++) {
            const float4* w4 = (const float4*)(wb + cl*12);
            float4 wa = w4[0], wc = w4[1];
            float wv[9] = {wa.x, wa.y, wa.z, wa.w, wc.x, wc.y, wc.z, wc.w, wb[cl*12+8]};
            win_fma(acc[cl], wv, p);
        }
    }
#pragma unroll
    for (int cl = 0; cl < 4; cl++) {
        int co = grp*4 + cl;
        float v = fmaxf(fmaxf(acc[cl][0], acc[cl][1]), fmaxf(acc[cl][2], acc[cl][3])) + bias[co];
        g_a2[(size_t)n*A2_PER + co*36 + pos] = fmaxf(v, 0.f);
    }
}

// ---------------- conv3: 32->32 on bn2(a2) 6x6 -> 4x4, relu ----------------
#define CONV3_SMEM ((12288 + 4608) * 4)
__global__ void __launch_bounds__(256) k_conv3(const float* __restrict__ w,
                                               const float* __restrict__ bias) {
    extern __shared__ float sm[];
    float* sw  = sm;             // 12288: repacked [ci][co][12]
    float* sin = sm + 12288;     // 4608: 4 samples x [32][36]
    int n0 = blockIdx.x * 4, tid = threadIdx.x;

    for (int i = tid; i < 9216; i += 256) {
        int co = i / 288, r = i % 288, ci = r / 9, k = r % 9;
        sw[(ci*32 + co)*12 + k] = w[i];
    }
    for (int i = tid; i < 4608; i += 256) {
        int s = i / 1152, j = i % 1152, c = j / 36;
        sin[i] = fmaf(g_a2[(size_t)(n0 + s)*A2_PER + j], g_g2[c], g_b2[c]);
    }
    __syncthreads();

    int s = tid / 64, r = tid % 64, pos = r % 16, grp = r / 16;  // 4 groups x 8 co
    int py = pos / 4, px = pos % 4;
    float acc[8];
#pragma unroll
    for (int a = 0; a < 8; a++) acc[a] = 0.f;

    for (int ci = 0; ci < 32; ci++) {
        float p[3][3];
        const float* sp = sin + s*1152 + ci*36 + py*6 + px;
#pragma unroll
        for (int ky = 0; ky < 3; ky++)
#pragma unroll
            for (int kx = 0; kx < 3; kx++) p[ky][kx] = sp[ky*6 + kx];
        const float* wb = sw + (ci*32 + grp*8)*12;
#pragma unroll
        for (int cl = 0; cl < 8; cl++) {
            const float4* w4 = (const float4*)(wb + cl*12);
            float4 wa = w4[0], wc = w4[1];
            float wv[9] = {wa.x, wa.y, wa.z, wa.w, wc.x, wc.y, wc.z, wc.w, wb[cl*12+8]};
            float a = acc[cl];
#pragma unroll
            for (int ky = 0; ky < 3; ky++)
#pragma unroll
                for (int kx = 0; kx < 3; kx++) a = fmaf(wv[ky*3+kx], p[ky][kx], a);
            acc[cl] = a;
        }
    }
#pragma unroll
    for (int cl = 0; cl < 8; cl++) {
        int co = grp*8 + cl;
        g_hp[(size_t)(n0 + s)*H_PER + co*16 + pos] = fmaxf(acc[cl] + bias[co], 0.f);
    }
}

// ---------------- VQ + blend + FC1 + FC2 + log_softmax (one block per sample) ----------------
__global__ void __launch_bounds__(128) k_vqfc(const float* __restrict__ cb,
                                              const float* __restrict__ fc1w,
                                              const float* __restrict__ fc1b,
                                              const float* __restrict__ fc2w,
                                              const float* __restrict__ fc2b,
                                              float* __restrict__ out) {
    __shared__ float scb[KCB*32];
    __shared__ float scbsq[KCB];
    __shared__ float hs[512];
    __shared__ float bl[512];
    __shared__ float z1[64];
    __shared__ int   idxs[16];
    __shared__ float wred[4];
    int n = blockIdx.x, tid = threadIdx.x;
    unsigned full = 0xffffffffu;

    for (int i = tid; i < KCB*32; i += 128) scb[i] = cb[i];
    if (tid < KCB) scbsq[tid] = g_cbsq[tid];
    for (int i = tid; i < 512; i += 128) {
        int c = i >> 4;
        float v = fmaf(g_hp[(size_t)n*H_PER + i], g_g3[c], g_b3[c]);
        hs[i] = v;
        out[H_OFF + (size_t)n*512 + i] = v;   // h output
    }
    __syncthreads();

    // VQ argmin: 16 positions x 8 code-subsets
    int pos = tid >> 3, sub = tid & 7;
    float z[32];
#pragma unroll
    for (int c = 0; c < 32; c++) z[c] = hs[c*16 + pos];
    float zz = 0.f;
#pragma unroll
    for (int c = 0; c < 32; c++) zz = fmaf(z[c], z[c], zz);
    float bd = INFINITY; int bi = 0;
    for (int k = sub; k < KCB; k += 8) {
        const float* cp = scb + k*32;
        float dot = 0.f;
#pragma unroll
        for (int c = 0; c < 32; c++) dot = fmaf(cp[c], z[c], dot);
        float d = zz + scbsq[k] - 2.f*dot;
        if (d < bd) { bd = d; bi = k; }
    }
#pragma unroll
    for (int off = 4; off; off >>= 1) {
        float od = __shfl_down_sync(full, bd, off, 8);
        int   oi = __shfl_down_sync(full, bi, off, 8);
        if (od < bd || (od == bd && oi < bi)) { bd = od; bi = oi; }
    }
    if (sub == 0) idxs[pos] = bi;
    __syncthreads();

    // recon / blended / vq partial
    float vqs = 0.f;
    for (int i = tid; i < 512; i += 128) {
        int c = i >> 4, p2 = i & 15;
        float q = scb[idxs[p2]*32 + c];
        float zv = hs[i];
        float df = q - zv;
        vqs = fmaf(df, df, vqs);
        out[RECON_OFF + (size_t)n*512 + i] = q;
        bl[i] = fmaf(0.5f, q, zv);
    }
    vqs = wredsum(vqs);
    if ((tid & 31) == 0) wred[tid >> 5] = vqs;
    __syncthreads();
    if (tid == 0) atomicAdd(&g_vq, wred[0] + wred[1] + wred[2] + wred[3]);

    // fc1: 64 outputs, warp-per-output rounds
    int warp = tid >> 5, lane = tid & 31;
    for (int r = 0; r < 16; r++) {
        int o = warp*16 + r;
        const float* wp = fc1w + o*512;
        float a = 0.f;
#pragma unroll
        for (int t = 0; t < 16; t++) a = fmaf(wp[lane + 32*t], bl[lane + 32*t], a);
        a = wredsum(a);
        if (lane == 0) z1[o] = fmaxf(a + fc1b[o], 0.f);
    }
    __syncthreads();

    // fc2 + log_softmax (warp 0)
    if (warp == 0) {
        float y = -INFINITY;
        if (lane < 10) {
            const float* wp = fc2w + lane*64;
            float a = 0.f;
#pragma unroll
            for (int j = 0; j < 64; j++) a = fmaf(wp[j], z1[j], a);
            y = a + fc2b[lane];
        }
        float m = y;
#pragma unroll
        for (int off = 16; off; off >>= 1) m = fmaxf(m, __shfl_xor_sync(full, m, off));
        float e = (lane < 10) ? expf(y - m) : 0.f;
        float ssum = e;
#pragma unroll
        for (int off = 16; off; off >>= 1) ssum += __shfl_xor_sync(full, ssum, off);
        if (lane < 10) out[LP_OFF + (size_t)n*10 + lane] = y - m - logf(ssum);
    }
}

__global__ void k_final(float* __restrict__ out) {
    out[LOSS_OFF] = 1.25f * g_vq / (float)(B * 16 * 32);
}

// ---------------- launch ----------------
extern "C" void kernel_launch(void* const* d_in, const int* in_sizes, int n_in,
                              void* d_out, int out_size) {
    const float* x      = (const float*)d_in[0];
    const float* c1w    = (const float*)d_in[1];
    const float* c1b    = (const float*)d_in[2];
    const float* bn1s   = (const float*)d_in[3];
    const float* bn1b   = (const float*)d_in[4];
    const float* c2w    = (const float*)d_in[5];
    const float* c2b    = (const float*)d_in[6];
    const float* bn2s   = (const float*)d_in[7];
    const float* bn2b   = (const float*)d_in[8];
    const float* c3w    = (const float*)d_in[9];
    const float* c3b    = (const float*)d_in[10];
    const float* bn3s   = (const float*)d_in[11];
    const float* bn3b   = (const float*)d_in[12];
    const float* cb     = (const float*)d_in[13];
    const float* fc1w   = (const float*)d_in[14];
    const float* fc1b   = (const float*)d_in[15];
    const float* fc2w   = (const float*)d_in[16];
    const float* fc2b   = (const float*)d_in[17];
    float* out = (float*)d_out;

    cudaFuncSetAttribute(k_conv2, cudaFuncAttributeMaxDynamicSharedMemorySize, CONV2_SMEM);
    cudaFuncSetAttribute(k_conv3, cudaFuncAttributeMaxDynamicSharedMemorySize, CONV3_SMEM);

    k_init<<<1, 256>>>(cb);
    k_conv1<<<B, 256>>>(x, c1w, c1b);
    { dim3 g(64, 64); k_stats<<<g, 256>>>(0); }
    k_bncoef<<<1, 64>>>(0, bn1s, bn1b, 2048.f * 225.f);
    k_conv2<<<B, 288, CONV2_SMEM>>>(c2w, c2b);
    { dim3 g(32, 64); k_stats<<<g, 256>>>(1); }
    k_bncoef<<<1, 32>>>(1, bn2s, bn2b, 2048.f * 36.f);
    k_conv3<<<B/4, 256, CONV3_SMEM>>>(c3w, c3b);
    { dim3 g(32, 64); k_stats<<<g, 256>>>(2); }
    k_bncoef<<<1, 32>>>(2, bn3s, bn3b, 2048.f * 16.f);
    k_vqfc<<<B, 128>>>(cb, fc1w, fc1b, fc2w, fc2b, out);
    k_final<<<1, 1>>>(out);
}

// round 3
// speedup vs baseline: 1.0804x; 1.0804x over previous
#include <cuda_runtime.h>
#include <math.h>

#define B 2048
#define C1 64
#define A1_HW 225
#define A1_PER (C1*A1_HW)     // 14400
#define C2 32
#define A2_HW 36
#define A2_PER (C2*A2_HW)     // 1152
#define H_PER 512
#define KCB 100
#define BN_EPS 1e-5f

#define RECON_OFF 0
#define H_OFF     (B*H_PER)
#define LOSS_OFF  (2*B*H_PER)
#define LP_OFF    (2*B*H_PER + 1)

typedef unsigned long long u64;

// ---------------- device scratch ----------------
__device__ float g_a1[B*A1_PER];          // conv1 out [n][co][225]
__device__ float g_a2[B*A2_PER];          // conv2 out, POSITION-MAJOR [n][36][32]
__device__ float g_hp[B*H_PER];           // conv3 out [n][co][16]
__device__ float2 g_w1p[3*64*10];         // conv1 weights dup-paired (w,w)
__device__ float2 g_w2p[64*16*10];        // conv2 weights co-paired (w[2cp], w[2cp+1])
__device__ float  g_w3p[32*32*12];        // conv3 weights 12-padded
__device__ float g_sum1[64], g_ssq1[64], g_g1[64], g_b1[64];
__device__ float g_sum2[32], g_ssq2[32], g_g2[32], g_b2[32];
__device__ float g_sum3[32], g_ssq3[32], g_g3[32], g_b3[32];
__device__ float g_cbsq[KCB];
__device__ float g_vq;

__device__ __forceinline__ float wredsum(float v) {
#pragma unroll
    for (int o = 16; o; o >>= 1) v += __shfl_down_sync(0xffffffffu, v, o);
    return v;
}

// packed f32x2 helpers
__device__ __forceinline__ u64 pack2(float x, float y) {
    u64 r; asm("mov.b64 %0, {%1,%2};" : "=l"(r) : "f"(x), "f"(y)); return r;
}
__device__ __forceinline__ u64 fma2(u64 a, u64 b, u64 c) {
    u64 d; asm("fma.rn.f32x2 %0, %1, %2, %3;" : "=l"(d) : "l"(a), "l"(b), "l"(c)); return d;
}
__device__ __forceinline__ float2 unpack2(u64 a) {
    float2 f; asm("mov.b64 {%0,%1}, %2;" : "=f"(f.x), "=f"(f.y) : "l"(a)); return f;
}

// ---------------- init ----------------
__global__ void k_init(const float* __restrict__ cb) {
    int t = threadIdx.x;
    if (t < 64) { g_sum1[t] = 0.f; g_ssq1[t] = 0.f; }
    if (t < 32) { g_sum2[t] = 0.f; g_ssq2[t] = 0.f; g_sum3[t] = 0.f; g_ssq3[t] = 0.f; }
    if (t == 0) g_vq = 0.f;
    if (t < KCB) {
        float s = 0.f;
#pragma unroll
        for (int c = 0; c < 32; c++) { float v = cb[t*32+c]; s = fmaf(v, v, s); }
        g_cbsq[t] = s;
    }
}

// ---------------- weight repack (once) ----------------
__global__ void k_repack(const float* __restrict__ w1, const float* __restrict__ w2,
                         const float* __restrict__ w3) {
    int t = blockIdx.x * blockDim.x + threadIdx.x;
    if (t < 1920) {                       // conv1: [ci][co][10] dup pairs
        int k = t % 10, r = t / 10, ci = r / 64, co = r % 64;
        float v = (k < 9) ? w1[co*27 + ci*9 + k] : 0.f;
        g_w1p[t] = make_float2(v, v);
    }
    if (t < 10240) {                      // conv2: [ci][cp][10] co-pairs
        int k = t % 10, r = t / 10, ci = r / 16, cp = r % 16;
        float a = 0.f, b = 0.f;
        if (k < 9) { a = w2[(2*cp)*576 + ci*9 + k]; b = w2[(2*cp+1)*576 + ci*9 + k]; }
        g_w2p[t] = make_float2(a, b);
    }
    if (t < 12288) {                      // conv3: [ci][co][12]
        int k = t % 12, r = t / 12, ci = r / 32, co = r % 32;
        g_w3p[t] = (k < 9) ? w3[co*288 + ci*9 + k] : 0.f;
    }
}

// ---------------- conv1: 3->64 on 32x32, pool->15x15, relu (f32x2) ----------------
__global__ void __launch_bounds__(256) k_conv1(const float* __restrict__ x,
                                               const float* __restrict__ bias) {
    __shared__ __align__(16) float  sx[3*32*34];     // pitch 34
    __shared__ __align__(16) float2 sw[1920];        // dup pairs [ci][co][10]
    __shared__ float sb[64];
    int n = blockIdx.x, tid = threadIdx.x;

    const float4* x4 = (const float4*)(x + (size_t)n * 3072);
    for (int i = tid; i < 768; i += 256) {
        float4 v = x4[i];
        int e = i * 4, ci = e >> 10, rem = e & 1023, y = rem >> 5, xc = rem & 31;
        float* d = sx + ci*1088 + y*34 + xc;
        d[0] = v.x; d[1] = v.y; d[2] = v.z; d[3] = v.w;
    }
    {
        const float4* wsrc = (const float4*)g_w1p;
        float4* wdst = (float4*)sw;
        for (int i = tid; i < 960; i += 256) wdst[i] = wsrc[i];
    }
    if (tid < 64) sb[tid] = bias[tid];
    __syncthreads();

    for (int it = tid; it < 1800; it += 256) {       // 225 pos x 8 co-groups
        int pos = it % 225, cg = it / 225;
        int py2 = (pos / 15) * 2, px2 = (pos % 15) * 2;
        u64 acc01[8], acc23[8];
#pragma unroll
        for (int c = 0; c < 8; c++) { acc01[c] = 0ull; acc23[c] = 0ull; }

#pragma unroll
        for (int ci = 0; ci < 3; ci++) {
            const float* spb = sx + ci*1088 + py2*34 + px2;
            u64 pr[4][3];
#pragma unroll
            for (int r = 0; r < 4; r++) {
                float2 q0 = *(const float2*)(spb + r*34);
                float2 q1 = *(const float2*)(spb + r*34 + 2);
                pr[r][0] = pack2(q0.x, q0.y);
                pr[r][1] = pack2(q0.y, q1.x);
                pr[r][2] = pack2(q1.x, q1.y);
            }
            const ulonglong2* wv = (const ulonglong2*)(sw + (ci*64 + cg*8)*10);
#pragma unroll
            for (int co = 0; co < 8; co++) {
                ulonglong2 wa = wv[co*5+0], wb = wv[co*5+1], wc = wv[co*5+2],
                           wd = wv[co*5+3], we = wv[co*5+4];
                u64 wk[9] = {wa.x, wa.y, wb.x, wb.y, wc.x, wc.y, wd.x, wd.y, we.x};
#pragma unroll
                for (int ky = 0; ky < 3; ky++)
#pragma unroll
                    for (int kx = 0; kx < 3; kx++) {
                        acc01[co] = fma2(wk[ky*3+kx], pr[ky  ][kx], acc01[co]);
                        acc23[co] = fma2(wk[ky*3+kx], pr[ky+1][kx], acc23[co]);
                    }
            }
        }
#pragma unroll
        for (int co = 0; co < 8; co++) {
            float2 a = unpack2(acc01[co]), b2v = unpack2(acc23[co]);
            int cog = cg*8 + co;
            float v = fmaxf(fmaxf(a.x, a.y), fmaxf(b2v.x, b2v.y)) + sb[cog];
            g_a1[(size_t)n*A1_PER + cog*225 + pos] = fmaxf(v, 0.f);
        }
    }
}

// ---------------- stats for stage0 only ----------------
__global__ void k_stats0() {
    int c = blockIdx.x, tid = threadIdx.x;
    float s = 0.f, s2 = 0.f;
    for (int n = blockIdx.y; n < B; n += gridDim.y) {
        const float* p = g_a1 + ((size_t)n*64 + c)*225;
        for (int i = tid; i < 225; i += blockDim.x) { float v = p[i]; s += v; s2 = fmaf(v, v, s2); }
    }
    __shared__ float rs[8], rq[8];
    s = wredsum(s); s2 = wredsum(s2);
    int wid = tid >> 5, lane = tid & 31;
    if (lane == 0) { rs[wid] = s; rq[wid] = s2; }
    __syncthreads();
    if (tid == 0) {
        float a1 = 0.f, a2 = 0.f;
        for (int w = 0; w < 8; w++) { a1 += rs[w]; a2 += rq[w]; }
        atomicAdd(g_sum1 + c, a1); atomicAdd(g_ssq1 + c, a2);
    }
}

// ---------------- BN coefficients ----------------
__global__ void k_bncoef(int stage, const float* __restrict__ scale,
                         const float* __restrict__ bias, float count) {
    float *sum, *ssq, *g, *bo; int C;
    if (stage == 0)      { sum = g_sum1; ssq = g_ssq1; g = g_g1; bo = g_b1; C = 64; }
    else if (stage == 1) { sum = g_sum2; ssq = g_ssq2; g = g_g2; bo = g_b2; C = 32; }
    else                 { sum = g_sum3; ssq = g_ssq3; g = g_g3; bo = g_b3; C = 32; }
    int c = threadIdx.x;
    if (c < C) {
        float m = sum[c] / count;
        float v = fmaxf(ssq[c] / count - m*m, 0.f);
        float gg = scale[c] / sqrtf(v + BN_EPS);
        g[c] = gg;
        bo[c] = bias[c] - m * gg;
    }
}

// ---------------- conv2: 64->32 on 15x15, pool->6x6, relu, fused stats (f32x2) ----------------
// smem: sin [64][15][16] (15360 f), sw2 10240 float2 (20480 f), sred 2x288 f
#define C2_SIN   0
#define C2_SW    15360
#define C2_SRED  35840
#define CONV2_SMEM ((15360 + 20480 + 576) * 4)
__global__ void __launch_bounds__(288) k_conv2(const float* __restrict__ bias) {
    extern __shared__ __align__(16) float sm[];
    float* sin = sm + C2_SIN;
    float2* sw2 = (float2*)(sm + C2_SW);
    float* sred  = sm + C2_SRED;
    float* sred2 = sm + C2_SRED + 288;
    float* sconv = sm;                        // alias over sin after phase A
    int n = blockIdx.x, tid = threadIdx.x;

    for (int i = tid; i < 14400; i += 288) {
        int c = i / 225, rem = i % 225, y = rem / 15, xx = rem % 15;
        sin[c*240 + y*16 + xx] = fmaf(g_a1[(size_t)n*A1_PER + i], g_g1[c], g_b1[c]);
    }
    {
        const float4* wsrc = (const float4*)g_w2p;
        float4* wdst = (float4*)sw2;
        for (int i = tid; i < 5120; i += 288) wdst[i] = wsrc[i];
    }
    __syncthreads();

    // phase A: one thread per conv position (12x12), 16 co (8 pairs) per thread
    int pos = tid % 144, cog = tid / 144;     // cog in {0,1}
    int y0 = pos / 12, x0 = pos % 12;
    u64 acc[8];
#pragma unroll
    for (int j = 0; j < 8; j++) acc[j] = 0ull;

    const float* spb = sin + y0*16 + x0;
    for (int ci = 0; ci < 64; ci++) {
        float p[9];
#pragma unroll
        for (int r = 0; r < 3; r++)
#pragma unroll
            for (int c = 0; c < 3; c++) p[r*3+c] = spb[ci*240 + r*16 + c];
        u64 pp[9];
#pragma unroll
        for (int k = 0; k < 9; k++) pp[k] = pack2(p[k], p[k]);
        const ulonglong2* wv = (const ulonglong2*)(sw2 + (ci*16 + cog*8)*10);
#pragma unroll
        for (int j = 0; j < 8; j++) {
            ulonglong2 wa = wv[j*5+0], wb = wv[j*5+1], wc = wv[j*5+2],
                       wd = wv[j*5+3], we = wv[j*5+4];
            u64 wk[9] = {wa.x, wa.y, wb.x, wb.y, wc.x, wc.y, wd.x, wd.y, we.x};
            u64 a = acc[j];
#pragma unroll
            for (int k = 0; k < 9; k++) a = fma2(wk[k], pp[k], a);
            acc[j] = a;
        }
    }
    __syncthreads();    // all sin reads done before aliasing

    // write conv outputs to pool buffer [32][145]
#pragma unroll
    for (int j = 0; j < 8; j++) {
        float2 v = unpack2(acc[j]);
        int co = cog*16 + 2*j;
        sconv[co*145 + pos]     = v.x;
        sconv[(co+1)*145 + pos] = v.y;
    }
    __syncthreads();

    // phase B: pool + bias + relu + write + stats
    int co = tid & 31;                        // 288 % 32 == 0 -> constant per thread
    float bc = bias[co];
    float s = 0.f, s2 = 0.f;
#pragma unroll
    for (int k = 0; k < 4; k++) {
        int pp2 = k*9 + (tid >> 5);           // pooled pos 0..35
        int py = pp2 / 6, px = pp2 % 6;
        const float* cbase = sconv + co*145;
        int c00 = (2*py)*12 + 2*px;
        float v = fmaxf(fmaxf(cbase[c00], cbase[c00+1]),
                        fmaxf(cbase[c00+12], cbase[c00+13])) + bc;
        v = fmaxf(v, 0.f);
        g_a2[(size_t)n*A2_PER + pp2*32 + co] = v;   // position-major, coalesced
        s += v; s2 = fmaf(v, v, s2);
    }
    sred[tid] = s; sred2[tid] = s2;
    __syncthreads();
    if (tid < 32) {
        float S = 0.f, S2 = 0.f;
#pragma unroll
        for (int k = 0; k < 9; k++) { S += sred[tid + k*32]; S2 += sred2[tid + k*32]; }
        atomicAdd(g_sum2 + tid, S); atomicAdd(g_ssq2 + tid, S2);
    }
}

// ---------------- conv3: 32->32 on 6x6 -> 4x4, relu, fused stats ----------------
// smem: sw3 12288 f, sin2 4*36*33=4752 f, ssum/sssq 64 f
#define C3_SW   0
#define C3_SIN  12288
#define C3_ST   17040
#define CONV3_SMEM ((12288 + 4752 + 64) * 4)
__global__ void __launch_bounds__(256) k_conv3(const float* __restrict__ bias) {
    extern __shared__ __align__(16) float sm3[];
    float* sw3 = sm3 + C3_SW;
    float* sin2 = sm3 + C3_SIN;
    float* ssum = sm3 + C3_ST;
    float* sssq = sm3 + C3_ST + 32;
    int n0 = blockIdx.x * 4, tid = threadIdx.x;

    {
        const float4* wsrc = (const float4*)g_w3p;
        float4* wdst = (float4*)sw3;
        for (int i = tid; i < 3072; i += 256) wdst[i] = wsrc[i];
    }
    for (int i = tid; i < 4608; i += 256) {
        int s = i / 1152, j = i % 1152, pos = j / 32, c = j & 31;
        sin2[s*1188 + pos*33 + c] = fmaf(g_a2[(size_t)(n0+s)*A2_PER + j], g_g2[c], g_b2[c]);
    }
    if (tid < 32) { ssum[tid] = 0.f; sssq[tid] = 0.f; }
    __syncthreads();

    int s = tid / 64, r = tid % 64, pos = r % 16, grp = r / 16;
    int py = pos / 4, px = pos % 4;
    float acc[8];
#pragma unroll
    for (int a = 0; a < 8; a++) acc[a] = 0.f;

    const float* sb2 = sin2 + s*1188;
    for (int ci = 0; ci < 32; ci++) {
        float p[9];
#pragma unroll
        for (int ky = 0; ky < 3; ky++)
#pragma unroll
            for (int kx = 0; kx < 3; kx++) p[ky*3+kx] = sb2[((py+ky)*6 + px+kx)*33 + ci];
        const float* wb = sw3 + (ci*32 + grp*8)*12;
#pragma unroll
        for (int cl = 0; cl < 8; cl++) {
            const float4* w4 = (const float4*)(wb + cl*12);
            float4 wa = w4[0], wc = w4[1];
            float wv[9] = {wa.x, wa.y, wa.z, wa.w, wc.x, wc.y, wc.z, wc.w, wb[cl*12+8]};
            float a = acc[cl];
#pragma unroll
            for (int k = 0; k < 9; k++) a = fmaf(wv[k], p[k], a);
            acc[cl] = a;
        }
    }
#pragma unroll
    for (int cl = 0; cl < 8; cl++) {
        int co = grp*8 + cl;
        float v = fmaxf(acc[cl] + bias[co], 0.f);
        g_hp[(size_t)(n0+s)*H_PER + co*16 + pos] = v;
        atomicAdd(&ssum[co], v);
        atomicAdd(&sssq[co], v*v);
    }
    __syncthreads();
    if (tid < 32) {
        atomicAdd(g_sum3 + tid, ssum[tid]);
        atomicAdd(g_ssq3 + tid, sssq[tid]);
    }
}

// ---------------- VQ + blend + FC1 + FC2 + log_softmax ----------------
__global__ void __launch_bounds__(128) k_vqfc(const float* __restrict__ cb,
                                              const float* __restrict__ fc1w,
                                              const float* __restrict__ fc1b,
                                              const float* __restrict__ fc2w,
                                              const float* __restrict__ fc2b,
                                              float* __restrict__ out) {
    __shared__ float scb[KCB*32];
    __shared__ float scbsq[KCB];
    __shared__ float hs[512];
    __shared__ float bl[512];
    __shared__ float z1[64];
    __shared__ int   idxs[16];
    __shared__ float wred[4];
    int n = blockIdx.x, tid = threadIdx.x;
    unsigned full = 0xffffffffu;

    for (int i = tid; i < KCB*32; i += 128) scb[i] = cb[i];
    if (tid < KCB) scbsq[tid] = g_cbsq[tid];
    for (int i = tid; i < 512; i += 128) {
        int c = i >> 4;
        float v = fmaf(g_hp[(size_t)n*H_PER + i], g_g3[c], g_b3[c]);
        hs[i] = v;
        out[H_OFF + (size_t)n*512 + i] = v;
    }
    __syncthreads();

    int pos = tid >> 3, sub = tid & 7;
    float z[32];
#pragma unroll
    for (int c = 0; c < 32; c++) z[c] = hs[c*16 + pos];
    float zz = 0.f;
#pragma unroll
    for (int c = 0; c < 32; c++) zz = fmaf(z[c], z[c], zz);
    float bd = INFINITY; int bi = 0;
    for (int k = sub; k < KCB; k += 8) {
        const float* cp = scb + k*32;
        float dot = 0.f;
#pragma unroll
        for (int c = 0; c < 32; c++) dot = fmaf(cp[c], z[c], dot);
        float d = zz + scbsq[k] - 2.f*dot;
        if (d < bd) { bd = d; bi = k; }
    }
#pragma unroll
    for (int off = 4; off; off >>= 1) {
        float od = __shfl_down_sync(full, bd, off, 8);
        int   oi = __shfl_down_sync(full, bi, off, 8);
        if (od < bd || (od == bd && oi < bi)) { bd = od; bi = oi; }
    }
    if (sub == 0) idxs[pos] = bi;
    __syncthreads();

    float vqs = 0.f;
    for (int i = tid; i < 512; i += 128) {
        int c = i >> 4, p2 = i & 15;
        float q = scb[idxs[p2]*32 + c];
        float zv = hs[i];
        float df = q - zv;
        vqs = fmaf(df, df, vqs);
        out[RECON_OFF + (size_t)n*512 + i] = q;
        bl[i] = fmaf(0.5f, q, zv);
    }
    vqs = wredsum(vqs);
    if ((tid & 31) == 0) wred[tid >> 5] = vqs;
    __syncthreads();
    if (tid == 0) atomicAdd(&g_vq, wred[0] + wred[1] + wred[2] + wred[3]);

    int warp = tid >> 5, lane = tid & 31;
    for (int r = 0; r < 16; r++) {
        int o = warp*16 + r;
        const float* wp = fc1w + o*512;
        float a = 0.f;
#pragma unroll
        for (int t = 0; t < 16; t++) a = fmaf(wp[lane + 32*t], bl[lane + 32*t], a);
        a = wredsum(a);
        if (lane == 0) z1[o] = fmaxf(a + fc1b[o], 0.f);
    }
    __syncthreads();

    if (warp == 0) {
        float y = -INFINITY;
        if (lane < 10) {
            const float* wp = fc2w + lane*64;
            float a = 0.f;
#pragma unroll
            for (int j = 0; j < 64; j++) a = fmaf(wp[j], z1[j], a);
            y = a + fc2b[lane];
        }
        float m = y;
#pragma unroll
        for (int off = 16; off; off >>= 1) m = fmaxf(m, __shfl_xor_sync(full, m, off));
        float e = (lane < 10) ? expf(y - m) : 0.f;
        float ssum = e;
#pragma unroll
        for (int off = 16; off; off >>= 1) ssum += __shfl_xor_sync(full, ssum, off);
        if (lane < 10) out[LP_OFF + (size_t)n*10 + lane] = y - m - logf(ssum);
    }
}

__global__ void k_final(float* __restrict__ out) {
    out[LOSS_OFF] = 1.25f * g_vq / (float)(B * 16 * 32);
}

// ---------------- launch ----------------
extern "C" void kernel_launch(void* const* d_in, const int* in_sizes, int n_in,
                              void* d_out, int out_size) {
    const float* x      = (const float*)d_in[0];
    const float* c1w    = (const float*)d_in[1];
    const float* c1b    = (const float*)d_in[2];
    const float* bn1s   = (const float*)d_in[3];
    const float* bn1b   = (const float*)d_in[4];
    const float* c2w    = (const float*)d_in[5];
    const float* c2b    = (const float*)d_in[6];
    const float* bn2s   = (const float*)d_in[7];
    const float* bn2b   = (const float*)d_in[8];
    const float* c3w    = (const float*)d_in[9];
    const float* c3b    = (const float*)d_in[10];
    const float* bn3s   = (const float*)d_in[11];
    const float* bn3b   = (const float*)d_in[12];
    const float* cb     = (const float*)d_in[13];
    const float* fc1w   = (const float*)d_in[14];
    const float* fc1b   = (const float*)d_in[15];
    const float* fc2w   = (const float*)d_in[16];
    const float* fc2b   = (const float*)d_in[17];
    float* out = (float*)d_out;

    cudaFuncSetAttribute(k_conv2, cudaFuncAttributeMaxDynamicSharedMemorySize, CONV2_SMEM);
    cudaFuncSetAttribute(k_conv3, cudaFuncAttributeMaxDynamicSharedMemorySize, CONV3_SMEM);

    k_init<<<1, 256>>>(cb);                                   // 0
    k_repack<<<48, 256>>>(c1w, c2w, c3w);                     // 1  (FIX: 48 blocks covers 12288)
    k_conv1<<<B, 256>>>(x, c1b);                              // 2
    { dim3 g(64, 64); k_stats0<<<g, 256>>>(); }               // 3
    k_bncoef<<<1, 64>>>(0, bn1s, bn1b, 2048.f * 225.f);       // 4
    k_conv2<<<B, 288, CONV2_SMEM>>>(c2b);                     // 5  <- ncu capture
    k_bncoef<<<1, 32>>>(1, bn2s, bn2b, 2048.f * 36.f);        // 6
    k_conv3<<<B/4, 256, CONV3_SMEM>>>(c3b);                   // 7
    k_bncoef<<<1, 32>>>(2, bn3s, bn3b, 2048.f * 16.f);        // 8
    k_vqfc<<<B, 128>>>(cb, fc1w, fc1b, fc2w, fc2b, out);      // 9
    k_final<<<1, 1>>>(out);                                   // 10
}